// round 2
// baseline (speedup 1.0000x reference)
#include <cuda_runtime.h>
#include <cstdint>
#include <cstddef>

// Problem constants
#define BATCH 4
#define CC    256
#define HH_   96
#define WW_   96
#define HW    (HH_ * WW_)        // 9216
#define NPIX  (BATCH * HW)       // 36864
#define NK    33

// ---------------- device scratch (no runtime allocation allowed) ----------------
__device__ float g_Mt[CC * CC];                 // Wg^T Wf           [c1][c2]
__device__ float g_v[CC];                       // Wf^T bg
__device__ float g_G[(size_t)BATCH * CC * HW];  // Mt @ Ft  (BCHW)   37.75 MB
__device__ float g_beta[NPIX];                  // v . Ft per pixel

// ---------------- star-offset generators (constexpr, fold under unroll) ---------
__host__ __device__ constexpr int offA(int k) {
    if (k == 0) return 0;
    int s = (k - 1) / 8 + 1, r = (k - 1) % 8;
    int a = (r < 3) ? -1 : (r < 5 ? 0 : 1);
    return a * s;
}
__host__ __device__ constexpr int offB(int k) {
    if (k == 0) return 0;
    int s = (k - 1) / 8 + 1, r = (k - 1) % 8;
    int b = (r < 3) ? (r - 1) : (r == 3 ? -1 : (r == 4 ? 1 : r - 6));
    return b * s;
}

// ================= Kernel A: Mt[c1][c2] = sum_o Wg[o,c1]*Wf[o,c2] ================
__global__ void kMt(const float* __restrict__ Wf, const float* __restrict__ Wg) {
    __shared__ float gs[32][16];
    __shared__ float fs[32][16];
    const int tx = threadIdx.x, ty = threadIdx.y;      // 16x16
    const int t  = ty * 16 + tx;
    const int c1b = blockIdx.y * 16, c2b = blockIdx.x * 16;
    float acc = 0.f;
    for (int o0 = 0; o0 < CC; o0 += 32) {
        #pragma unroll
        for (int j = 0; j < 2; j++) {
            int i = t + j * 256;
            int r = i >> 4, q = i & 15;
            gs[r][q] = Wg[(o0 + r) * CC + c1b + q];
            fs[r][q] = Wf[(o0 + r) * CC + c2b + q];
        }
        __syncthreads();
        #pragma unroll
        for (int o = 0; o < 32; o++) acc += gs[o][ty] * fs[o][tx];
        __syncthreads();
    }
    g_Mt[(c1b + ty) * CC + (c2b + tx)] = acc;
}

// ================= Kernel V: v[c] = sum_o Wf[o,c]*bg[o] ==========================
__global__ void kV(const float* __restrict__ Wf, const float* __restrict__ bg) {
    __shared__ float bgs[CC];
    const int c = threadIdx.x;
    bgs[c] = bg[c];
    __syncthreads();
    float acc = 0.f;
    #pragma unroll 8
    for (int o = 0; o < CC; o++) acc += Wf[o * CC + c] * bgs[o];
    g_v[c] = acc;
}

// ================= Kernel G: G[b,c1,p] = sum_c2 Mt[c1,c2]*Ft[b,c2,p] =============
// 128(c1) x 128(pix) block tile, BK=8, 256 threads, 8x8 micro-tile.
__global__ void __launch_bounds__(256, 2) kG(const float* __restrict__ Ft) {
    constexpr int BM = 128, BN = 128, BK = 8;
    __shared__ __align__(16) float As[BK][BM];   // transposed Mt chunk
    __shared__ __align__(16) float Bs[BK][BN];
    const int t  = threadIdx.x;
    const int tx = t & 15, ty = t >> 4;
    const int b  = blockIdx.z;
    const int p0 = blockIdx.x * BN;
    const int m0 = blockIdx.y * BM;
    const float* FtB = Ft + (size_t)b * CC * HW + p0;
    float*       GB  = g_G + (size_t)b * CC * HW + p0;

    const int am = t >> 1, ak = (t & 1) * 4;     // As source indices
    const int bk = t >> 5, bn = (t & 31) * 4;    // Bs source indices

    float acc[8][8];
    #pragma unroll
    for (int i = 0; i < 8; i++)
        #pragma unroll
        for (int j = 0; j < 8; j++) acc[i][j] = 0.f;

    // prefetch chunk 0
    float4 av = *(const float4*)&g_Mt[(m0 + am) * CC + ak];
    float4 bv = *(const float4*)&FtB[(size_t)bk * HW + bn];

    for (int k0 = 0; k0 < CC; k0 += BK) {
        __syncthreads();
        As[ak + 0][am] = av.x; As[ak + 1][am] = av.y;
        As[ak + 2][am] = av.z; As[ak + 3][am] = av.w;
        *(float4*)&Bs[bk][bn] = bv;
        __syncthreads();
        if (k0 + BK < CC) {   // prefetch next chunk while computing
            av = *(const float4*)&g_Mt[(m0 + am) * CC + k0 + BK + ak];
            bv = *(const float4*)&FtB[(size_t)(k0 + BK + bk) * HW + bn];
        }
        #pragma unroll
        for (int kk = 0; kk < BK; kk++) {
            float4 a0 = *(const float4*)&As[kk][ty * 8];
            float4 a1 = *(const float4*)&As[kk][ty * 8 + 4];
            float4 b0 = *(const float4*)&Bs[kk][tx * 8];
            float4 b1 = *(const float4*)&Bs[kk][tx * 8 + 4];
            float ar[8] = {a0.x, a0.y, a0.z, a0.w, a1.x, a1.y, a1.z, a1.w};
            float br[8] = {b0.x, b0.y, b0.z, b0.w, b1.x, b1.y, b1.z, b1.w};
            #pragma unroll
            for (int i = 0; i < 8; i++)
                #pragma unroll
                for (int j = 0; j < 8; j++) acc[i][j] += ar[i] * br[j];
        }
    }
    #pragma unroll
    for (int i = 0; i < 8; i++) {
        const int m = m0 + ty * 8 + i;
        float4 o0 = make_float4(acc[i][0], acc[i][1], acc[i][2], acc[i][3]);
        float4 o1 = make_float4(acc[i][4], acc[i][5], acc[i][6], acc[i][7]);
        *(float4*)&GB[(size_t)m * HW + tx * 8]     = o0;
        *(float4*)&GB[(size_t)m * HW + tx * 8 + 4] = o1;
    }
}

// ================= Kernel beta: beta[p] = sum_c v[c]*Ft[b,c,p] ===================
__global__ void kBeta(const float* __restrict__ Ft) {
    __shared__ float vs[CC];
    const int t = threadIdx.x;
    vs[t] = g_v[t];
    __syncthreads();
    const int p  = blockIdx.x * 256 + t;
    const int b  = p / HW;
    const int pp = p - b * HW;
    const float* base = Ft + (size_t)b * CC * HW + pp;
    float acc = 0.f;
    #pragma unroll 8
    for (int c = 0; c < CC; c++) acc += vs[c] * base[(size_t)c * HW];
    g_beta[p] = acc;
}

// ================= Kernel Attn: logits -> softmax -> aggregate ===================
// Tile 32(w) x 8(h), 256 threads (warp == one pixel row -> conflict-free LDS).
// Halo 16x40 of one channel plane, double buffered, loads prefetched 2 deep.
__global__ void __launch_bounds__(256) kAttn(const float* __restrict__ Ft,
                                             const float* __restrict__ Fte,
                                             float* __restrict__ out) {
    constexpr int TW = 32, TH = 8, HALO = 4;
    constexpr int SW = TW + 2 * HALO;   // 40
    constexpr int SH = TH + 2 * HALO;   // 16
    constexpr int SN = SH * SW;         // 640
    __shared__ float Sh[2][SN];

    const int t  = threadIdx.x;
    const int tx = t & 31, ty = t >> 5;
    const int b  = blockIdx.z;
    const int w0 = blockIdx.x * TW, h0 = blockIdx.y * TH;
    const int h = h0 + ty, w = w0 + tx;
    const int pix = h * WW_ + w;
    const size_t plane = (size_t)b * CC * HW;
    const int sbase = (ty + HALO) * SW + (tx + HALO);

    // Precompute per-thread halo staging map (constant across channels).
    int  sidx[3], soff[3];
    bool svld[3];
    #pragma unroll
    for (int j = 0; j < 3; j++) {
        int i = t + j * 256;
        sidx[j] = i;
        int r = i / SW, cc = i - r * SW;
        int hh = h0 - HALO + r, ww = w0 - HALO + cc;
        svld[j] = (i < SN) && ((unsigned)hh < HH_) && ((unsigned)ww < WW_);
        soff[j] = hh * WW_ + ww;
    }
    float stg[3];

#define STAGE_LOAD(src)                                        \
    { _Pragma("unroll")                                        \
      for (int j = 0; j < 3; j++)                              \
          stg[j] = svld[j] ? (src)[soff[j]] : 0.f; }
#define STAGE_STORE(dst)                                       \
    { _Pragma("unroll")                                        \
      for (int j = 0; j < 3; j++)                              \
          if (sidx[j] < SN) (dst)[sidx[j]] = stg[j]; }

    // ---- init logits with beta(q) and validity mask ----
    STAGE_LOAD(g_beta + b * HW);
    STAGE_STORE(Sh[0]);
    __syncthreads();
    float lg[NK];
    #pragma unroll
    for (int k = 0; k < NK; k++) {
        const int a = offA(k), bo = offB(k);
        const bool valid = ((unsigned)(h + a) < HH_) && ((unsigned)(w + bo) < WW_);
        lg[k] = valid ? Sh[0][sbase + a * SW + bo] : -1e30f;
    }
    __syncthreads();

    // ---- phase 1: logits += Fe(p) * G(q), loop channels ----
    const float* Gb = g_G + plane;
    const float* Fb = Fte + plane;
    STAGE_LOAD(Gb);
    STAGE_STORE(Sh[0]);
    STAGE_LOAD(Gb + HW);
    float fe = Fb[pix];
    for (int c = 0; c < CC; c++) {
        const int buf = c & 1;
        __syncthreads();
        if (c + 1 < CC) STAGE_STORE(Sh[buf ^ 1]);                       // data for c+1
        if (c + 2 < CC) STAGE_LOAD(Gb + (size_t)(c + 2) * HW);          // prefetch c+2
        const float fcur = fe;
        if (c + 1 < CC) fe = Fb[(size_t)(c + 1) * HW + pix];
        const float* S = Sh[buf];
        #pragma unroll
        for (int k = 0; k < NK; k++)
            lg[k] += fcur * S[sbase + offA(k) * SW + offB(k)];
    }

    // ---- softmax over 33 ----
    float m = lg[0];
    #pragma unroll
    for (int k = 1; k < NK; k++) m = fmaxf(m, lg[k]);
    float s = 0.f;
    #pragma unroll
    for (int k = 0; k < NK; k++) { lg[k] = expf(lg[k] - m); s += lg[k]; }
    const float inv = 1.0f / s;
    #pragma unroll
    for (int k = 0; k < NK; k++) lg[k] *= inv;

    // ---- phase 2: out[c,p] = sum_k w_k * Ft[c, q_k] ----
    const float* Fa = Ft + plane;
    float*       Ob = out + plane;
    STAGE_LOAD(Fa);
    STAGE_STORE(Sh[0]);
    STAGE_LOAD(Fa + HW);
    for (int c = 0; c < CC; c++) {
        const int buf = c & 1;
        __syncthreads();
        if (c + 1 < CC) STAGE_STORE(Sh[buf ^ 1]);
        if (c + 2 < CC) STAGE_LOAD(Fa + (size_t)(c + 2) * HW);
        const float* S = Sh[buf];
        float acc = 0.f;
        #pragma unroll
        for (int k = 0; k < NK; k++)
            acc += lg[k] * S[sbase + offA(k) * SW + offB(k)];
        Ob[(size_t)c * HW + pix] = acc;
    }
#undef STAGE_LOAD
#undef STAGE_STORE
}

// =================================== launch ======================================
extern "C" void kernel_launch(void* const* d_in, const int* in_sizes, int n_in,
                              void* d_out, int out_size) {
    const float* Ft  = (const float*)d_in[0];
    const float* Fte = (const float*)d_in[1];
    const float* Wf  = (const float*)d_in[2];
    // const float* bf = (const float*)d_in[3];   // softmax-invariant terms only
    const float* Wg  = (const float*)d_in[4];
    const float* bg  = (const float*)d_in[5];
    float* out = (float*)d_out;

    kMt<<<dim3(16, 16), dim3(16, 16)>>>(Wf, Wg);
    kV<<<1, 256>>>(Wf, bg);
    kG<<<dim3(HW / 128, CC / 128, BATCH), 256>>>(Ft);
    kBeta<<<NPIX / 256, 256>>>(Ft);
    kAttn<<<dim3(WW_ / 32, HH_ / 8, BATCH), 256>>>(Ft, Fte, out);
}

// round 4
// speedup vs baseline: 1.0875x; 1.0875x over previous
#include <cuda_runtime.h>
#include <cuda_bf16.h>
#include <cstdint>
#include <cstddef>

// Problem constants
#define BATCH 4
#define CC    256
#define HH_   96
#define WW_   96
#define HW    (HH_ * WW_)        // 9216
#define NPIX  (BATCH * HW)       // 36864
#define NK    33

// ---------------- device scratch ----------------
__device__ __nv_bfloat16 g_MtHi[CC * CC];
__device__ __nv_bfloat16 g_MtLo[CC * CC];
__device__ float g_v[CC];
__device__ float g_G[(size_t)BATCH * CC * HW];
__device__ float g_beta[NPIX];

// ---------------- star offsets ----------------
__host__ __device__ constexpr int offA(int k) {
    if (k == 0) return 0;
    int s = (k - 1) / 8 + 1, r = (k - 1) % 8;
    int a = (r < 3) ? -1 : (r < 5 ? 0 : 1);
    return a * s;
}
__host__ __device__ constexpr int offB(int k) {
    if (k == 0) return 0;
    int s = (k - 1) / 8 + 1, r = (k - 1) % 8;
    int b = (r < 3) ? (r - 1) : (r == 3 ? -1 : (r == 4 ? 1 : r - 6));
    return b * s;
}

// ---------------- helpers ----------------
__device__ __forceinline__ uint32_t smem_u32(const void* p) {
    uint32_t a;
    asm("{ .reg .u64 t; cvta.to.shared.u64 t, %1; cvt.u32.u64 %0, t; }" : "=r"(a) : "l"(p));
    return a;
}
__device__ __forceinline__ void ldmx4(uint32_t* r, uint32_t a) {
    asm volatile("ldmatrix.sync.aligned.m8n8.x4.shared.b16 {%0,%1,%2,%3}, [%4];"
                 : "=r"(r[0]), "=r"(r[1]), "=r"(r[2]), "=r"(r[3]) : "r"(a));
}
__device__ __forceinline__ void ldmx4t(uint32_t* r, uint32_t a) {
    asm volatile("ldmatrix.sync.aligned.m8n8.x4.trans.shared.b16 {%0,%1,%2,%3}, [%4];"
                 : "=r"(r[0]), "=r"(r[1]), "=r"(r[2]), "=r"(r[3]) : "r"(a));
}
#define MMA16816(acc, a, b0, b1)                                              \
    asm volatile("mma.sync.aligned.m16n8k16.row.col.f32.bf16.bf16.f32 "       \
                 "{%0,%1,%2,%3},{%4,%5,%6,%7},{%8,%9},{%0,%1,%2,%3};"         \
                 : "+f"((acc)[0]), "+f"((acc)[1]), "+f"((acc)[2]), "+f"((acc)[3]) \
                 : "r"((a)[0]), "r"((a)[1]), "r"((a)[2]), "r"((a)[3]),        \
                   "r"(b0), "r"(b1))

__device__ __forceinline__ uint32_t packHi(float x, float y) {
    __nv_bfloat162 h = __floats2bfloat162_rn(x, y);
    return *reinterpret_cast<uint32_t*>(&h);
}
__device__ __forceinline__ uint32_t packLo(float x, float y, uint32_t hpack) {
    __nv_bfloat162 h = *reinterpret_cast<__nv_bfloat162*>(&hpack);
    __nv_bfloat162 l = __floats2bfloat162_rn(x - __bfloat162float(h.x),
                                             y - __bfloat162float(h.y));
    return *reinterpret_cast<uint32_t*>(&l);
}

// ================= Kernel A: Mt = Wg^T Wf, split to bf16 hi/lo ================
__global__ void kMt(const float* __restrict__ Wf, const float* __restrict__ Wg) {
    __shared__ float gs[32][16];
    __shared__ float fs[32][16];
    const int tx = threadIdx.x, ty = threadIdx.y;
    const int t  = ty * 16 + tx;
    const int c1b = blockIdx.y * 16, c2b = blockIdx.x * 16;
    float acc = 0.f;
    for (int o0 = 0; o0 < CC; o0 += 32) {
        #pragma unroll
        for (int j = 0; j < 2; j++) {
            int i = t + j * 256;
            int r = i >> 4, q = i & 15;
            gs[r][q] = Wg[(o0 + r) * CC + c1b + q];
            fs[r][q] = Wf[(o0 + r) * CC + c2b + q];
        }
        __syncthreads();
        #pragma unroll
        for (int o = 0; o < 32; o++) acc += gs[o][ty] * fs[o][tx];
        __syncthreads();
    }
    __nv_bfloat16 hi = __float2bfloat16_rn(acc);
    __nv_bfloat16 lo = __float2bfloat16_rn(acc - __bfloat162float(hi));
    g_MtHi[(c1b + ty) * CC + (c2b + tx)] = hi;
    g_MtLo[(c1b + ty) * CC + (c2b + tx)] = lo;
}

// ================= Kernel V: v[c] = sum_o Wf[o,c]*bg[o] ========================
__global__ void kV(const float* __restrict__ Wf, const float* __restrict__ bg) {
    __shared__ float bgs[CC];
    const int c = threadIdx.x;
    bgs[c] = bg[c];
    __syncthreads();
    float acc = 0.f;
    #pragma unroll 8
    for (int o = 0; o < CC; o++) acc += Wf[o * CC + c] * bgs[o];
    g_v[c] = acc;
}

// ================= Kernel G: HMMA bf16-split GEMM + fused beta =================
// CTA tile: BM=128 (c1) x BN=128 (px) x BK=32. 8 warps (2M x 4N), warp 64x32.
// 3 terms per k16: Ahi*Bhi + Ahi*Blo + Alo*Bhi  (fp32 accumulation).
// Smem: A padded rows (80B pitch, bank-clean), B [k][n] XOR-swizzled chunks.
#define SMV   0
#define SMAH  1024
#define SMAL  (SMAH + 128 * 80)      // 11264
#define SMBH  (SMAL + 128 * 80)      // 21504
#define SMBL  (SMBH + 8192)          // 29696
#define SMTOT (SMBL + 8192)          // 37888

__global__ void __launch_bounds__(256) kG(const float* __restrict__ Ft) {
    __shared__ __align__(16) char sm[SMTOT];
    const uint32_t sb = smem_u32(sm);
    const int t = threadIdx.x;
    const int lane = t & 31, wid = t >> 5;
    const int wm = wid & 1, wn = wid >> 1;          // warp 64(M) x 32(N)

    const int b  = blockIdx.z;
    const int p0 = blockIdx.x * 128;                // pixel base within batch plane
    const int m0 = blockIdx.y * 128;                // c1 base
    const bool doBeta = (blockIdx.y == 0);
    const float* FtB = Ft + (size_t)b * CC * HW + p0;

    float* vs = (float*)(sm + SMV);
    vs[t] = g_v[t];

    float acc[4][4][4];
    #pragma unroll
    for (int i = 0; i < 4; i++)
        #pragma unroll
        for (int j = 0; j < 4; j++)
            #pragma unroll
            for (int r = 0; r < 4; r++) acc[i][j][r] = 0.f;
    float bacc[16];
    #pragma unroll
    for (int j = 0; j < 16; j++) bacc[j] = 0.f;

    // per-thread load mapping
    const int arow = t >> 1;                         // A: row, 2 chunks each
    const int kq   = t >> 3;                         // B: k row (0..31)
    const int nslt = t & 7;                          // B: 16-px slot

    for (int kc = 0; kc < 8; kc++) {
        const int k0 = kc * 32;
        __syncthreads();
        // ---- A chunk: 128 rows x 32 k, hi + lo ----
        #pragma unroll
        for (int j = 0; j < 2; j++) {
            const int ch = (t & 1) * 2 + j;
            const size_t src = (size_t)(m0 + arow) * (CC * 2) + (size_t)k0 * 2 + ch * 16;
            *(uint4*)(sm + SMAH + arow * 80 + ch * 16) = *(const uint4*)((const char*)g_MtHi + src);
            *(uint4*)(sm + SMAL + arow * 80 + ch * 16) = *(const uint4*)((const char*)g_MtLo + src);
        }
        // ---- B chunk: 32 k x 128 px fp32 -> hi/lo bf16, + beta FMA ----
        {
            const float* src = FtB + (size_t)(k0 + kq) * HW + nslt * 16;
            const float vk = vs[k0 + kq];
            #pragma unroll
            for (int c = 0; c < 2; c++) {
                float4 f0 = *(const float4*)(src + c * 8);
                float4 f1 = *(const float4*)(src + c * 8 + 4);
                uint32_t h0 = packHi(f0.x, f0.y), h1 = packHi(f0.z, f0.w);
                uint32_t h2 = packHi(f1.x, f1.y), h3 = packHi(f1.z, f1.w);
                uint32_t l0 = packLo(f0.x, f0.y, h0), l1 = packLo(f0.z, f0.w, h1);
                uint32_t l2 = packLo(f1.x, f1.y, h2), l3 = packLo(f1.z, f1.w, h3);
                const int ch = ((nslt * 2 + c) ^ (kq & 7));
                *(uint4*)(sm + SMBH + kq * 256 + ch * 16) = make_uint4(h0, h1, h2, h3);
                *(uint4*)(sm + SMBL + kq * 256 + ch * 16) = make_uint4(l0, l1, l2, l3);
                if (doBeta) {
                    bacc[c * 8 + 0] = fmaf(vk, f0.x, bacc[c * 8 + 0]);
                    bacc[c * 8 + 1] = fmaf(vk, f0.y, bacc[c * 8 + 1]);
                    bacc[c * 8 + 2] = fmaf(vk, f0.z, bacc[c * 8 + 2]);
                    bacc[c * 8 + 3] = fmaf(vk, f0.w, bacc[c * 8 + 3]);
                    bacc[c * 8 + 4] = fmaf(vk, f1.x, bacc[c * 8 + 4]);
                    bacc[c * 8 + 5] = fmaf(vk, f1.y, bacc[c * 8 + 5]);
                    bacc[c * 8 + 6] = fmaf(vk, f1.z, bacc[c * 8 + 6]);
                    bacc[c * 8 + 7] = fmaf(vk, f1.w, bacc[c * 8 + 7]);
                }
            }
        }
        __syncthreads();
        // ---- compute: 2 k16 steps x 3 terms ----
        #pragma unroll
        for (int ks = 0; ks < 2; ks++) {
            const int kk = ks * 16;
            const int aRow = wm * 64 + (lane & 15);
            const int aKb  = kk * 2 + (lane & 16);
            const int bK   = kk + (lane & 15);
            uint32_t FA[4][4], FB[2][4], FB2[2][4];
            #pragma unroll
            for (int mi = 0; mi < 4; mi++)
                ldmx4(FA[mi], sb + SMAH + (aRow + mi * 16) * 80 + aKb);
            #pragma unroll
            for (int p = 0; p < 2; p++) {
                const int nb = wn * 64 + p * 32 + (lane & 16);
                const int ch = ((nb >> 4) ^ (bK & 7));
                ldmx4t(FB[p], sb + SMBH + bK * 256 + (ch << 4));
            }
            #pragma unroll
            for (int mi = 0; mi < 4; mi++)
                #pragma unroll
                for (int p = 0; p < 2; p++) {
                    MMA16816(acc[mi][p * 2 + 0], FA[mi], FB[p][0], FB[p][1]);
                    MMA16816(acc[mi][p * 2 + 1], FA[mi], FB[p][2], FB[p][3]);
                }
            #pragma unroll
            for (int p = 0; p < 2; p++) {
                const int nb = wn * 64 + p * 32 + (lane & 16);
                const int ch = ((nb >> 4) ^ (bK & 7));
                ldmx4t(FB2[p], sb + SMBL + bK * 256 + (ch << 4));
            }
            #pragma unroll
            for (int mi = 0; mi < 4; mi++)
                #pragma unroll
                for (int p = 0; p < 2; p++) {
                    MMA16816(acc[mi][p * 2 + 0], FA[mi], FB2[p][0], FB2[p][1]);
                    MMA16816(acc[mi][p * 2 + 1], FA[mi], FB2[p][2], FB2[p][3]);
                }
            #pragma unroll
            for (int mi = 0; mi < 4; mi++)
                ldmx4(FA[mi], sb + SMAL + (aRow + mi * 16) * 80 + aKb);
            #pragma unroll
            for (int mi = 0; mi < 4; mi++)
                #pragma unroll
                for (int p = 0; p < 2; p++) {
                    MMA16816(acc[mi][p * 2 + 0], FA[mi], FB[p][0], FB[p][1]);
                    MMA16816(acc[mi][p * 2 + 1], FA[mi], FB[p][2], FB[p][3]);
                }
        }
    }

    // ---- epilogue: direct float2 stores of accumulators ----
    {
        float* GB = g_G + (size_t)b * CC * HW + p0;
        const int g = lane >> 2, t4 = lane & 3;
        #pragma unroll
        for (int mi = 0; mi < 4; mi++) {
            const int row = m0 + wm * 64 + mi * 16 + g;
            #pragma unroll
            for (int nb = 0; nb < 4; nb++) {
                const int px = wn * 32 + nb * 8 + t4 * 2;
                *(float2*)(GB + (size_t)row * HW + px) =
                    make_float2(acc[mi][nb][0], acc[mi][nb][1]);
                *(float2*)(GB + (size_t)(row + 8) * HW + px) =
                    make_float2(acc[mi][nb][2], acc[mi][nb][3]);
            }
        }
    }

    // ---- beta: cross-k reduction through smem ----
    if (doBeta) {
        __syncthreads();
        float* bsm = (float*)(sm + SMAH);       // 16KB, reuses A region
        #pragma unroll
        for (int j = 0; j < 16; j += 4)
            *(float4*)(bsm + t * 16 + j) =
                make_float4(bacc[j], bacc[j + 1], bacc[j + 2], bacc[j + 3]);
        __syncthreads();
        if (t < 128) {
            const int slot = t >> 4, jj = t & 15;
            float s = 0.f;
            #pragma unroll 8
            for (int kg = 0; kg < 32; kg++)
                s += bsm[(kg * 8 + slot) * 16 + jj];
            g_beta[b * HW + p0 + t] = s;
        }
    }
}

// ================= Kernel Attn: logits -> softmax -> aggregate ==================
__global__ void __launch_bounds__(256) kAttn(const float* __restrict__ Ft,
                                             const float* __restrict__ Fte,
                                             float* __restrict__ out) {
    constexpr int TW = 32, TH = 8, HALO = 4;
    constexpr int SW = TW + 2 * HALO;   // 40
    constexpr int SH = TH + 2 * HALO;   // 16
    constexpr int SN = SH * SW;         // 640
    __shared__ float Sh[2][SN];

    const int t  = threadIdx.x;
    const int tx = t & 31, ty = t >> 5;
    const int b  = blockIdx.z;
    const int w0 = blockIdx.x * TW, h0 = blockIdx.y * TH;
    const int h = h0 + ty, w = w0 + tx;
    const int pix = h * WW_ + w;
    const size_t plane = (size_t)b * CC * HW;
    const int sbase = (ty + HALO) * SW + (tx + HALO);

    int  sidx[3], soff[3];
    bool svld[3];
    #pragma unroll
    for (int j = 0; j < 3; j++) {
        int i = t + j * 256;
        sidx[j] = i;
        int r = i / SW, cc = i - r * SW;
        int hh = h0 - HALO + r, ww = w0 - HALO + cc;
        svld[j] = (i < SN) && ((unsigned)hh < HH_) && ((unsigned)ww < WW_);
        soff[j] = hh * WW_ + ww;
    }
    float stg[3];

#define STAGE_LOAD(src)                                        \
    { _Pragma("unroll")                                        \
      for (int j = 0; j < 3; j++)                              \
          stg[j] = svld[j] ? (src)[soff[j]] : 0.f; }
#define STAGE_STORE(dst)                                       \
    { _Pragma("unroll")                                        \
      for (int j = 0; j < 3; j++)                              \
          if (sidx[j] < SN) (dst)[sidx[j]] = stg[j]; }

    STAGE_LOAD(g_beta + b * HW);
    STAGE_STORE(Sh[0]);
    __syncthreads();
    float lg[NK];
    #pragma unroll
    for (int k = 0; k < NK; k++) {
        const int a = offA(k), bo = offB(k);
        const bool valid = ((unsigned)(h + a) < HH_) && ((unsigned)(w + bo) < WW_);
        lg[k] = valid ? Sh[0][sbase + a * SW + bo] : -1e30f;
    }
    __syncthreads();

    const float* Gb = g_G + plane;
    const float* Fb = Fte + plane;
    STAGE_LOAD(Gb);
    STAGE_STORE(Sh[0]);
    STAGE_LOAD(Gb + HW);
    float fe = Fb[pix];
    for (int c = 0; c < CC; c++) {
        const int buf = c & 1;
        __syncthreads();
        if (c + 1 < CC) STAGE_STORE(Sh[buf ^ 1]);
        if (c + 2 < CC) STAGE_LOAD(Gb + (size_t)(c + 2) * HW);
        const float fcur = fe;
        if (c + 1 < CC) fe = Fb[(size_t)(c + 1) * HW + pix];
        const float* S = Sh[buf];
        #pragma unroll
        for (int k = 0; k < NK; k++)
            lg[k] += fcur * S[sbase + offA(k) * SW + offB(k)];
    }

    float m = lg[0];
    #pragma unroll
    for (int k = 1; k < NK; k++) m = fmaxf(m, lg[k]);
    float s = 0.f;
    #pragma unroll
    for (int k = 0; k < NK; k++) { lg[k] = expf(lg[k] - m); s += lg[k]; }
    const float inv = 1.0f / s;
    #pragma unroll
    for (int k = 0; k < NK; k++) lg[k] *= inv;

    const float* Fa = Ft + plane;
    float*       Ob = out + plane;
    STAGE_LOAD(Fa);
    STAGE_STORE(Sh[0]);
    STAGE_LOAD(Fa + HW);
    for (int c = 0; c < CC; c++) {
        const int buf = c & 1;
        __syncthreads();
        if (c + 1 < CC) STAGE_STORE(Sh[buf ^ 1]);
        if (c + 2 < CC) STAGE_LOAD(Fa + (size_t)(c + 2) * HW);
        const float* S = Sh[buf];
        float acc = 0.f;
        #pragma unroll
        for (int k = 0; k < NK; k++)
            acc += lg[k] * S[sbase + offA(k) * SW + offB(k)];
        Ob[(size_t)c * HW + pix] = acc;
    }
#undef STAGE_LOAD
#undef STAGE_STORE
}

// =================================== launch ======================================
extern "C" void kernel_launch(void* const* d_in, const int* in_sizes, int n_in,
                              void* d_out, int out_size) {
    const float* Ft  = (const float*)d_in[0];
    const float* Fte = (const float*)d_in[1];
    const float* Wf  = (const float*)d_in[2];
    const float* Wg  = (const float*)d_in[4];
    const float* bg  = (const float*)d_in[5];
    float* out = (float*)d_out;

    kMt<<<dim3(16, 16), dim3(16, 16)>>>(Wf, Wg);
    kV<<<1, 256>>>(Wf, bg);
    kG<<<dim3(HW / 128, 2, BATCH), 256>>>(Ft);
    kAttn<<<dim3(WW_ / 32, HH_ / 8, BATCH), 256>>>(Ft, Fte, out);
}

// round 6
// speedup vs baseline: 1.7378x; 1.5979x over previous
#include <cuda_runtime.h>
#include <cuda_bf16.h>
#include <cstdint>
#include <cstddef>

// Problem constants
#define BATCH 4
#define CC    256
#define HH_   96
#define WW_   96
#define HW    (HH_ * WW_)        // 9216
#define NPIX  (BATCH * HW)       // 36864
#define NK    33

// ---------------- device scratch ----------------
__device__ __nv_bfloat16 g_MtHi[CC * CC];
__device__ __nv_bfloat16 g_MtLo[CC * CC];
__device__ float g_v[CC];
__device__ float g_G[(size_t)BATCH * CC * HW];
__device__ float g_beta[NPIX];

// ---------------- star offsets ----------------
__host__ __device__ constexpr int offA(int k) {
    if (k == 0) return 0;
    int s = (k - 1) / 8 + 1, r = (k - 1) % 8;
    int a = (r < 3) ? -1 : (r < 5 ? 0 : 1);
    return a * s;
}
__host__ __device__ constexpr int offB(int k) {
    if (k == 0) return 0;
    int s = (k - 1) / 8 + 1, r = (k - 1) % 8;
    int b = (r < 3) ? (r - 1) : (r == 3 ? -1 : (r == 4 ? 1 : r - 6));
    return b * s;
}

// ---------------- helpers ----------------
__device__ __forceinline__ uint32_t smem_u32(const void* p) {
    uint32_t a;
    asm("{ .reg .u64 t; cvta.to.shared.u64 t, %1; cvt.u32.u64 %0, t; }" : "=r"(a) : "l"(p));
    return a;
}
__device__ __forceinline__ void ldmx4(uint32_t* r, uint32_t a) {
    asm volatile("ldmatrix.sync.aligned.m8n8.x4.shared.b16 {%0,%1,%2,%3}, [%4];"
                 : "=r"(r[0]), "=r"(r[1]), "=r"(r[2]), "=r"(r[3]) : "r"(a));
}
__device__ __forceinline__ void ldmx4t(uint32_t* r, uint32_t a) {
    asm volatile("ldmatrix.sync.aligned.m8n8.x4.trans.shared.b16 {%0,%1,%2,%3}, [%4];"
                 : "=r"(r[0]), "=r"(r[1]), "=r"(r[2]), "=r"(r[3]) : "r"(a));
}
#define MMA16816(acc, a, b0, b1)                                              \
    asm volatile("mma.sync.aligned.m16n8k16.row.col.f32.bf16.bf16.f32 "       \
                 "{%0,%1,%2,%3},{%4,%5,%6,%7},{%8,%9},{%0,%1,%2,%3};"         \
                 : "+f"((acc)[0]), "+f"((acc)[1]), "+f"((acc)[2]), "+f"((acc)[3]) \
                 : "r"((a)[0]), "r"((a)[1]), "r"((a)[2]), "r"((a)[3]),        \
                   "r"(b0), "r"(b1))

__device__ __forceinline__ uint32_t packHi(float x, float y) {
    __nv_bfloat162 h = __floats2bfloat162_rn(x, y);
    return *reinterpret_cast<uint32_t*>(&h);
}
__device__ __forceinline__ uint32_t packLo(float x, float y, uint32_t hpack) {
    __nv_bfloat162 h = *reinterpret_cast<__nv_bfloat162*>(&hpack);
    __nv_bfloat162 l = __floats2bfloat162_rn(x - __bfloat162float(h.x),
                                             y - __bfloat162float(h.y));
    return *reinterpret_cast<uint32_t*>(&l);
}

// ================= Kernel A: Mt = Wg^T Wf, split to bf16 hi/lo ================
__global__ void kMt(const float* __restrict__ Wf, const float* __restrict__ Wg) {
    __shared__ float gs[32][16];
    __shared__ float fs[32][16];
    const int tx = threadIdx.x, ty = threadIdx.y;
    const int t  = ty * 16 + tx;
    const int c1b = blockIdx.y * 16, c2b = blockIdx.x * 16;
    float acc = 0.f;
    for (int o0 = 0; o0 < CC; o0 += 32) {
        #pragma unroll
        for (int j = 0; j < 2; j++) {
            int i = t + j * 256;
            int r = i >> 4, q = i & 15;
            gs[r][q] = Wg[(o0 + r) * CC + c1b + q];
            fs[r][q] = Wf[(o0 + r) * CC + c2b + q];
        }
        __syncthreads();
        #pragma unroll
        for (int o = 0; o < 32; o++) acc += gs[o][ty] * fs[o][tx];
        __syncthreads();
    }
    __nv_bfloat16 hi = __float2bfloat16_rn(acc);
    __nv_bfloat16 lo = __float2bfloat16_rn(acc - __bfloat162float(hi));
    g_MtHi[(c1b + ty) * CC + (c2b + tx)] = hi;
    g_MtLo[(c1b + ty) * CC + (c2b + tx)] = lo;
}

// ================= Kernel V: v[c] = sum_o Wf[o,c]*bg[o] ========================
__global__ void kV(const float* __restrict__ Wf, const float* __restrict__ bg) {
    __shared__ float bgs[CC];
    const int c = threadIdx.x;
    bgs[c] = bg[c];
    __syncthreads();
    float acc = 0.f;
    #pragma unroll 8
    for (int o = 0; o < CC; o++) acc += Wf[o * CC + c] * bgs[o];
    g_v[c] = acc;
}

// ================= Kernel G: HMMA bf16-split GEMM + fused beta =================
#define SMV   0
#define SMAH  1024
#define SMAL  (SMAH + 128 * 80)      // 11264
#define SMBH  (SMAL + 128 * 80)      // 21504
#define SMBL  (SMBH + 8192)          // 29696
#define SMTOT (SMBL + 8192)          // 37888

__global__ void __launch_bounds__(256) kG(const float* __restrict__ Ft) {
    __shared__ __align__(16) char sm[SMTOT];
    const uint32_t sb = smem_u32(sm);
    const int t = threadIdx.x;
    const int lane = t & 31, wid = t >> 5;
    const int wm = wid & 1, wn = wid >> 1;          // warp 64(M) x 32(N)

    const int b  = blockIdx.z;
    const int p0 = blockIdx.x * 128;
    const int m0 = blockIdx.y * 128;
    const bool doBeta = (blockIdx.y == 0);
    const float* FtB = Ft + (size_t)b * CC * HW + p0;

    float* vs = (float*)(sm + SMV);
    vs[t] = g_v[t];

    float acc[4][4][4];
    #pragma unroll
    for (int i = 0; i < 4; i++)
        #pragma unroll
        for (int j = 0; j < 4; j++)
            #pragma unroll
            for (int r = 0; r < 4; r++) acc[i][j][r] = 0.f;
    float bacc[16];
    #pragma unroll
    for (int j = 0; j < 16; j++) bacc[j] = 0.f;

    const int arow = t >> 1;
    const int kq   = t >> 3;
    const int nslt = t & 7;

    for (int kc = 0; kc < 8; kc++) {
        const int k0 = kc * 32;
        __syncthreads();
        #pragma unroll
        for (int j = 0; j < 2; j++) {
            const int ch = (t & 1) * 2 + j;
            const size_t src = (size_t)(m0 + arow) * (CC * 2) + (size_t)k0 * 2 + ch * 16;
            *(uint4*)(sm + SMAH + arow * 80 + ch * 16) = *(const uint4*)((const char*)g_MtHi + src);
            *(uint4*)(sm + SMAL + arow * 80 + ch * 16) = *(const uint4*)((const char*)g_MtLo + src);
        }
        {
            const float* src = FtB + (size_t)(k0 + kq) * HW + nslt * 16;
            const float vk = vs[k0 + kq];
            #pragma unroll
            for (int c = 0; c < 2; c++) {
                float4 f0 = *(const float4*)(src + c * 8);
                float4 f1 = *(const float4*)(src + c * 8 + 4);
                uint32_t h0 = packHi(f0.x, f0.y), h1 = packHi(f0.z, f0.w);
                uint32_t h2 = packHi(f1.x, f1.y), h3 = packHi(f1.z, f1.w);
                uint32_t l0 = packLo(f0.x, f0.y, h0), l1 = packLo(f0.z, f0.w, h1);
                uint32_t l2 = packLo(f1.x, f1.y, h2), l3 = packLo(f1.z, f1.w, h3);
                const int ch = ((nslt * 2 + c) ^ (kq & 7));
                *(uint4*)(sm + SMBH + kq * 256 + ch * 16) = make_uint4(h0, h1, h2, h3);
                *(uint4*)(sm + SMBL + kq * 256 + ch * 16) = make_uint4(l0, l1, l2, l3);
                if (doBeta) {
                    bacc[c * 8 + 0] = fmaf(vk, f0.x, bacc[c * 8 + 0]);
                    bacc[c * 8 + 1] = fmaf(vk, f0.y, bacc[c * 8 + 1]);
                    bacc[c * 8 + 2] = fmaf(vk, f0.z, bacc[c * 8 + 2]);
                    bacc[c * 8 + 3] = fmaf(vk, f0.w, bacc[c * 8 + 3]);
                    bacc[c * 8 + 4] = fmaf(vk, f1.x, bacc[c * 8 + 4]);
                    bacc[c * 8 + 5] = fmaf(vk, f1.y, bacc[c * 8 + 5]);
                    bacc[c * 8 + 6] = fmaf(vk, f1.z, bacc[c * 8 + 6]);
                    bacc[c * 8 + 7] = fmaf(vk, f1.w, bacc[c * 8 + 7]);
                }
            }
        }
        __syncthreads();
        #pragma unroll
        for (int ks = 0; ks < 2; ks++) {
            const int kk = ks * 16;
            const int aRow = wm * 64 + (lane & 15);
            const int aKb  = kk * 2 + (lane & 16);
            const int bK   = kk + (lane & 15);
            uint32_t FA[4][4], FB[2][4], FB2[2][4];
            #pragma unroll
            for (int mi = 0; mi < 4; mi++)
                ldmx4(FA[mi], sb + SMAH + (aRow + mi * 16) * 80 + aKb);
            #pragma unroll
            for (int p = 0; p < 2; p++) {
                const int nb = wn * 64 + p * 32 + (lane & 16);
                const int ch = ((nb >> 4) ^ (bK & 7));
                ldmx4t(FB[p], sb + SMBH + bK * 256 + (ch << 4));
            }
            #pragma unroll
            for (int mi = 0; mi < 4; mi++)
                #pragma unroll
                for (int p = 0; p < 2; p++) {
                    MMA16816(acc[mi][p * 2 + 0], FA[mi], FB[p][0], FB[p][1]);
                    MMA16816(acc[mi][p * 2 + 1], FA[mi], FB[p][2], FB[p][3]);
                }
            #pragma unroll
            for (int p = 0; p < 2; p++) {
                const int nb = wn * 64 + p * 32 + (lane & 16);
                const int ch = ((nb >> 4) ^ (bK & 7));
                ldmx4t(FB2[p], sb + SMBL + bK * 256 + (ch << 4));
            }
            #pragma unroll
            for (int mi = 0; mi < 4; mi++)
                #pragma unroll
                for (int p = 0; p < 2; p++) {
                    MMA16816(acc[mi][p * 2 + 0], FA[mi], FB2[p][0], FB2[p][1]);
                    MMA16816(acc[mi][p * 2 + 1], FA[mi], FB2[p][2], FB2[p][3]);
                }
            #pragma unroll
            for (int mi = 0; mi < 4; mi++)
                ldmx4(FA[mi], sb + SMAL + (aRow + mi * 16) * 80 + aKb);
            #pragma unroll
            for (int mi = 0; mi < 4; mi++)
                #pragma unroll
                for (int p = 0; p < 2; p++) {
                    MMA16816(acc[mi][p * 2 + 0], FA[mi], FB[p][0], FB[p][1]);
                    MMA16816(acc[mi][p * 2 + 1], FA[mi], FB[p][2], FB[p][3]);
                }
        }
    }

    {
        float* GB = g_G + (size_t)b * CC * HW + p0;
        const int g = lane >> 2, t4 = lane & 3;
        #pragma unroll
        for (int mi = 0; mi < 4; mi++) {
            const int row = m0 + wm * 64 + mi * 16 + g;
            #pragma unroll
            for (int nb = 0; nb < 4; nb++) {
                const int px = wn * 32 + nb * 8 + t4 * 2;
                *(float2*)(GB + (size_t)row * HW + px) =
                    make_float2(acc[mi][nb][0], acc[mi][nb][1]);
                *(float2*)(GB + (size_t)(row + 8) * HW + px) =
                    make_float2(acc[mi][nb][2], acc[mi][nb][3]);
            }
        }
    }

    if (doBeta) {
        __syncthreads();
        float* bsm = (float*)(sm + SMAH);
        #pragma unroll
        for (int j = 0; j < 16; j += 4)
            *(float4*)(bsm + t * 16 + j) =
                make_float4(bacc[j], bacc[j + 1], bacc[j + 2], bacc[j + 3]);
        __syncthreads();
        if (t < 128) {
            const int slot = t >> 4, jj = t & 15;
            float s = 0.f;
            #pragma unroll 8
            for (int kg = 0; kg < 32; kg++)
                s += bsm[(kg * 8 + slot) * 16 + jj];
            g_beta[b * HW + p0 + t] = s;
        }
    }
}

// ================= Kernel Attn: logits -> softmax -> aggregate ==================
// Tile 32(w) x 8(h), 256 threads. CH=4 channels per barrier iteration:
// 4 halo planes staged per group (10 independent LDGs/thread), double buffered.
__global__ void __launch_bounds__(256) kAttn(const float* __restrict__ Ft,
                                             const float* __restrict__ Fte,
                                             float* __restrict__ out) {
    constexpr int TW = 32, TH = 8, HALO = 4;
    constexpr int SW = TW + 2 * HALO;   // 40
    constexpr int SH = TH + 2 * HALO;   // 16
    constexpr int SN = SH * SW;         // 640
    constexpr int CH = 4;
    constexpr int SNC = SN * CH;        // 2560
    constexpr int NG = CC / CH;         // 64 groups
    __shared__ float Sh[2][SNC];

    const int t  = threadIdx.x;
    const int tx = t & 31, ty = t >> 5;
    const int b  = blockIdx.z;
    const int w0 = blockIdx.x * TW, h0 = blockIdx.y * TH;
    const int h = h0 + ty, w = w0 + tx;
    const int pix = h * WW_ + w;
    const size_t plane = (size_t)b * CC * HW;
    const int sbase = (ty + HALO) * SW + (tx + HALO);

    // per-thread 10-entry staging map over 4 contiguous planes
    int  soff[10];
    bool svld[10];
    #pragma unroll
    for (int j = 0; j < 10; j++) {
        int idx = t + j * 256;
        int q = idx / SN, i = idx - q * SN;
        int r = i / SW, cc = i - r * SW;
        int hh = h0 - HALO + r, ww = w0 - HALO + cc;
        svld[j] = ((unsigned)hh < HH_) && ((unsigned)ww < WW_);
        soff[j] = q * HW + hh * WW_ + ww;
    }
    float stg[10];

#define GLOAD(src)                                             \
    { _Pragma("unroll")                                        \
      for (int j = 0; j < 10; j++)                             \
          stg[j] = svld[j] ? (src)[soff[j]] : 0.f; }
#define GSTORE(dst)                                            \
    { _Pragma("unroll")                                        \
      for (int j = 0; j < 10; j++)                             \
          (dst)[t + j * 256] = stg[j]; }

    // ---- init logits with beta(q) and validity mask ----
    #pragma unroll
    for (int j = 0; j < 3; j++) {
        int i = t + j * 256;
        if (i < SN) {
            int r = i / SW, cc = i - r * SW;
            int hh = h0 - HALO + r, ww = w0 - HALO + cc;
            bool v = ((unsigned)hh < HH_) && ((unsigned)ww < WW_);
            Sh[0][i] = v ? g_beta[b * HW + hh * WW_ + ww] : 0.f;
        }
    }
    __syncthreads();
    float lg[NK];
    #pragma unroll
    for (int k = 0; k < NK; k++) {
        const int a = offA(k), bo = offB(k);
        const bool valid = ((unsigned)(h + a) < HH_) && ((unsigned)(w + bo) < WW_);
        lg[k] = valid ? Sh[0][sbase + a * SW + bo] : -1e30f;
    }
    __syncthreads();

    // ---- phase 1: logits += Fe(p) * G(q), 4 channels per barrier ----
    const float* Gb = g_G + plane;
    const float* Fb = Fte + plane;
    GLOAD(Gb);
    GSTORE(Sh[0]);
    GLOAD(Gb + CH * HW);
    float fe[CH], fen[CH];
    #pragma unroll
    for (int cc = 0; cc < CH; cc++) fe[cc] = Fb[(size_t)cc * HW + pix];
    for (int g = 0; g < NG; g++) {
        const int buf = g & 1;
        __syncthreads();
        if (g + 1 < NG) GSTORE(Sh[buf ^ 1]);
        if (g + 2 < NG) GLOAD(Gb + (size_t)(g + 2) * CH * HW);
        #pragma unroll
        for (int cc = 0; cc < CH; cc++)
            fen[cc] = (g + 1 < NG) ? Fb[(size_t)((g + 1) * CH + cc) * HW + pix] : 0.f;
        const float* S = Sh[buf];
        #pragma unroll
        for (int cc = 0; cc < CH; cc++) {
            const float fc = fe[cc];
            const float* Sc = S + cc * SN;
            #pragma unroll
            for (int k = 0; k < NK; k++)
                lg[k] += fc * Sc[sbase + offA(k) * SW + offB(k)];
        }
        #pragma unroll
        for (int cc = 0; cc < CH; cc++) fe[cc] = fen[cc];
    }

    // ---- softmax over 33 ----
    float m = lg[0];
    #pragma unroll
    for (int k = 1; k < NK; k++) m = fmaxf(m, lg[k]);
    float s = 0.f;
    #pragma unroll
    for (int k = 0; k < NK; k++) { lg[k] = expf(lg[k] - m); s += lg[k]; }
    const float inv = 1.0f / s;
    #pragma unroll
    for (int k = 0; k < NK; k++) lg[k] *= inv;

    // ---- phase 2: out[c,p] = sum_k w_k * Ft[c, q_k], 4 channels per barrier ----
    const float* Fa = Ft + plane;
    float*       Ob = out + plane;
    __syncthreads();
    GLOAD(Fa);
    GSTORE(Sh[0]);
    GLOAD(Fa + CH * HW);
    for (int g = 0; g < NG; g++) {
        const int buf = g & 1;
        __syncthreads();
        if (g + 1 < NG) GSTORE(Sh[buf ^ 1]);
        if (g + 2 < NG) GLOAD(Fa + (size_t)(g + 2) * CH * HW);
        const float* S = Sh[buf];
        #pragma unroll
        for (int cc = 0; cc < CH; cc++) {
            const float* Sc = S + cc * SN;
            float acc = 0.f;
            #pragma unroll
            for (int k = 0; k < NK; k++)
                acc += lg[k] * Sc[sbase + offA(k) * SW + offB(k)];
            Ob[(size_t)(g * CH + cc) * HW + pix] = acc;
        }
    }
#undef GLOAD
#undef GSTORE
}

// =================================== launch ======================================
extern "C" void kernel_launch(void* const* d_in, const int* in_sizes, int n_in,
                              void* d_out, int out_size) {
    const float* Ft  = (const float*)d_in[0];
    const float* Fte = (const float*)d_in[1];
    const float* Wf  = (const float*)d_in[2];
    const float* Wg  = (const float*)d_in[4];
    const float* bg  = (const float*)d_in[5];
    float* out = (float*)d_out;

    kMt<<<dim3(16, 16), dim3(16, 16)>>>(Wf, Wg);
    kV<<<1, 256>>>(Wf, bg);
    kG<<<dim3(HW / 128, 2, BATCH), 256>>>(Ft);
    kAttn<<<dim3(WW_ / 32, HH_ / 8, BATCH), 256>>>(Ft, Fte, out);
}

// round 7
// speedup vs baseline: 2.0484x; 1.1787x over previous
#include <cuda_runtime.h>
#include <cuda_bf16.h>
#include <cstdint>
#include <cstddef>

// Problem constants
#define BATCH 4
#define CC    256
#define HH_   96
#define WW_   96
#define HW    (HH_ * WW_)        // 9216
#define NPIX  (BATCH * HW)       // 36864
#define NK    33

// ---------------- device scratch ----------------
__device__ __nv_bfloat16 g_MtHi[CC * CC];
__device__ __nv_bfloat16 g_MtLo[CC * CC];
__device__ float g_v[CC];
__device__ float g_G[(size_t)BATCH * CC * HW];
__device__ float g_beta[NPIX];
__device__ float g_part[(size_t)2 * NK * NPIX];   // per-half partial logits, 9.7MB

// ---------------- star offsets ----------------
__host__ __device__ constexpr int offA(int k) {
    if (k == 0) return 0;
    int s = (k - 1) / 8 + 1, r = (k - 1) % 8;
    int a = (r < 3) ? -1 : (r < 5 ? 0 : 1);
    return a * s;
}
__host__ __device__ constexpr int offB(int k) {
    if (k == 0) return 0;
    int s = (k - 1) / 8 + 1, r = (k - 1) % 8;
    int b = (r < 3) ? (r - 1) : (r == 3 ? -1 : (r == 4 ? 1 : r - 6));
    return b * s;
}

// ---------------- helpers ----------------
__device__ __forceinline__ uint32_t smem_u32(const void* p) {
    uint32_t a;
    asm("{ .reg .u64 t; cvta.to.shared.u64 t, %1; cvt.u32.u64 %0, t; }" : "=r"(a) : "l"(p));
    return a;
}
__device__ __forceinline__ void ldmx4(uint32_t* r, uint32_t a) {
    asm volatile("ldmatrix.sync.aligned.m8n8.x4.shared.b16 {%0,%1,%2,%3}, [%4];"
                 : "=r"(r[0]), "=r"(r[1]), "=r"(r[2]), "=r"(r[3]) : "r"(a));
}
__device__ __forceinline__ void ldmx4t(uint32_t* r, uint32_t a) {
    asm volatile("ldmatrix.sync.aligned.m8n8.x4.trans.shared.b16 {%0,%1,%2,%3}, [%4];"
                 : "=r"(r[0]), "=r"(r[1]), "=r"(r[2]), "=r"(r[3]) : "r"(a));
}
#define MMA16816(acc, a, b0, b1)                                              \
    asm volatile("mma.sync.aligned.m16n8k16.row.col.f32.bf16.bf16.f32 "       \
                 "{%0,%1,%2,%3},{%4,%5,%6,%7},{%8,%9},{%0,%1,%2,%3};"         \
                 : "+f"((acc)[0]), "+f"((acc)[1]), "+f"((acc)[2]), "+f"((acc)[3]) \
                 : "r"((a)[0]), "r"((a)[1]), "r"((a)[2]), "r"((a)[3]),        \
                   "r"(b0), "r"(b1))

__device__ __forceinline__ uint32_t packHi(float x, float y) {
    __nv_bfloat162 h = __floats2bfloat162_rn(x, y);
    return *reinterpret_cast<uint32_t*>(&h);
}
__device__ __forceinline__ uint32_t packLo(float x, float y, uint32_t hpack) {
    __nv_bfloat162 h = *reinterpret_cast<__nv_bfloat162*>(&hpack);
    __nv_bfloat162 l = __floats2bfloat162_rn(x - __bfloat162float(h.x),
                                             y - __bfloat162float(h.y));
    return *reinterpret_cast<uint32_t*>(&l);
}

// ================= Kernel A: Mt = Wg^T Wf, split to bf16 hi/lo ================
__global__ void kMt(const float* __restrict__ Wf, const float* __restrict__ Wg) {
    __shared__ float gs[32][16];
    __shared__ float fs[32][16];
    const int tx = threadIdx.x, ty = threadIdx.y;
    const int t  = ty * 16 + tx;
    const int c1b = blockIdx.y * 16, c2b = blockIdx.x * 16;
    float acc = 0.f;
    for (int o0 = 0; o0 < CC; o0 += 32) {
        #pragma unroll
        for (int j = 0; j < 2; j++) {
            int i = t + j * 256;
            int r = i >> 4, q = i & 15;
            gs[r][q] = Wg[(o0 + r) * CC + c1b + q];
            fs[r][q] = Wf[(o0 + r) * CC + c2b + q];
        }
        __syncthreads();
        #pragma unroll
        for (int o = 0; o < 32; o++) acc += gs[o][ty] * fs[o][tx];
        __syncthreads();
    }
    __nv_bfloat16 hi = __float2bfloat16_rn(acc);
    __nv_bfloat16 lo = __float2bfloat16_rn(acc - __bfloat162float(hi));
    g_MtHi[(c1b + ty) * CC + (c2b + tx)] = hi;
    g_MtLo[(c1b + ty) * CC + (c2b + tx)] = lo;
}

// ================= Kernel V: v[c] = sum_o Wf[o,c]*bg[o] ========================
__global__ void kV(const float* __restrict__ Wf, const float* __restrict__ bg) {
    __shared__ float bgs[CC];
    const int c = threadIdx.x;
    bgs[c] = bg[c];
    __syncthreads();
    float acc = 0.f;
    #pragma unroll 8
    for (int o = 0; o < CC; o++) acc += Wf[o * CC + c] * bgs[o];
    g_v[c] = acc;
}

// ================= Kernel G: HMMA bf16-split GEMM + fused beta =================
#define SMV   0
#define SMAH  1024
#define SMAL  (SMAH + 128 * 80)      // 11264
#define SMBH  (SMAL + 128 * 80)      // 21504
#define SMBL  (SMBH + 8192)          // 29696
#define SMTOT (SMBL + 8192)          // 37888

__global__ void __launch_bounds__(256) kG(const float* __restrict__ Ft) {
    __shared__ __align__(16) char sm[SMTOT];
    const uint32_t sb = smem_u32(sm);
    const int t = threadIdx.x;
    const int lane = t & 31, wid = t >> 5;
    const int wm = wid & 1, wn = wid >> 1;          // warp 64(M) x 32(N)

    const int b  = blockIdx.z;
    const int p0 = blockIdx.x * 128;
    const int m0 = blockIdx.y * 128;
    const bool doBeta = (blockIdx.y == 0);
    const float* FtB = Ft + (size_t)b * CC * HW + p0;

    float* vs = (float*)(sm + SMV);
    vs[t] = g_v[t];

    float acc[4][4][4];
    #pragma unroll
    for (int i = 0; i < 4; i++)
        #pragma unroll
        for (int j = 0; j < 4; j++)
            #pragma unroll
            for (int r = 0; r < 4; r++) acc[i][j][r] = 0.f;
    float bacc[16];
    #pragma unroll
    for (int j = 0; j < 16; j++) bacc[j] = 0.f;

    const int arow = t >> 1;
    const int kq   = t >> 3;
    const int nslt = t & 7;

    for (int kc = 0; kc < 8; kc++) {
        const int k0 = kc * 32;
        __syncthreads();
        #pragma unroll
        for (int j = 0; j < 2; j++) {
            const int ch = (t & 1) * 2 + j;
            const size_t src = (size_t)(m0 + arow) * (CC * 2) + (size_t)k0 * 2 + ch * 16;
            *(uint4*)(sm + SMAH + arow * 80 + ch * 16) = *(const uint4*)((const char*)g_MtHi + src);
            *(uint4*)(sm + SMAL + arow * 80 + ch * 16) = *(const uint4*)((const char*)g_MtLo + src);
        }
        {
            const float* src = FtB + (size_t)(k0 + kq) * HW + nslt * 16;
            const float vk = vs[k0 + kq];
            #pragma unroll
            for (int c = 0; c < 2; c++) {
                float4 f0 = *(const float4*)(src + c * 8);
                float4 f1 = *(const float4*)(src + c * 8 + 4);
                uint32_t h0 = packHi(f0.x, f0.y), h1 = packHi(f0.z, f0.w);
                uint32_t h2 = packHi(f1.x, f1.y), h3 = packHi(f1.z, f1.w);
                uint32_t l0 = packLo(f0.x, f0.y, h0), l1 = packLo(f0.z, f0.w, h1);
                uint32_t l2 = packLo(f1.x, f1.y, h2), l3 = packLo(f1.z, f1.w, h3);
                const int ch = ((nslt * 2 + c) ^ (kq & 7));
                *(uint4*)(sm + SMBH + kq * 256 + ch * 16) = make_uint4(h0, h1, h2, h3);
                *(uint4*)(sm + SMBL + kq * 256 + ch * 16) = make_uint4(l0, l1, l2, l3);
                if (doBeta) {
                    bacc[c * 8 + 0] = fmaf(vk, f0.x, bacc[c * 8 + 0]);
                    bacc[c * 8 + 1] = fmaf(vk, f0.y, bacc[c * 8 + 1]);
                    bacc[c * 8 + 2] = fmaf(vk, f0.z, bacc[c * 8 + 2]);
                    bacc[c * 8 + 3] = fmaf(vk, f0.w, bacc[c * 8 + 3]);
                    bacc[c * 8 + 4] = fmaf(vk, f1.x, bacc[c * 8 + 4]);
                    bacc[c * 8 + 5] = fmaf(vk, f1.y, bacc[c * 8 + 5]);
                    bacc[c * 8 + 6] = fmaf(vk, f1.z, bacc[c * 8 + 6]);
                    bacc[c * 8 + 7] = fmaf(vk, f1.w, bacc[c * 8 + 7]);
                }
            }
        }
        __syncthreads();
        #pragma unroll
        for (int ks = 0; ks < 2; ks++) {
            const int kk = ks * 16;
            const int aRow = wm * 64 + (lane & 15);
            const int aKb  = kk * 2 + (lane & 16);
            const int bK   = kk + (lane & 15);
            uint32_t FA[4][4], FB[2][4], FB2[2][4];
            #pragma unroll
            for (int mi = 0; mi < 4; mi++)
                ldmx4(FA[mi], sb + SMAH + (aRow + mi * 16) * 80 + aKb);
            #pragma unroll
            for (int p = 0; p < 2; p++) {
                const int nb = wn * 64 + p * 32 + (lane & 16);
                const int ch = ((nb >> 4) ^ (bK & 7));
                ldmx4t(FB[p], sb + SMBH + bK * 256 + (ch << 4));
            }
            #pragma unroll
            for (int mi = 0; mi < 4; mi++)
                #pragma unroll
                for (int p = 0; p < 2; p++) {
                    MMA16816(acc[mi][p * 2 + 0], FA[mi], FB[p][0], FB[p][1]);
                    MMA16816(acc[mi][p * 2 + 1], FA[mi], FB[p][2], FB[p][3]);
                }
            #pragma unroll
            for (int p = 0; p < 2; p++) {
                const int nb = wn * 64 + p * 32 + (lane & 16);
                const int ch = ((nb >> 4) ^ (bK & 7));
                ldmx4t(FB2[p], sb + SMBL + bK * 256 + (ch << 4));
            }
            #pragma unroll
            for (int mi = 0; mi < 4; mi++)
                #pragma unroll
                for (int p = 0; p < 2; p++) {
                    MMA16816(acc[mi][p * 2 + 0], FA[mi], FB2[p][0], FB2[p][1]);
                    MMA16816(acc[mi][p * 2 + 1], FA[mi], FB2[p][2], FB2[p][3]);
                }
            #pragma unroll
            for (int mi = 0; mi < 4; mi++)
                ldmx4(FA[mi], sb + SMAL + (aRow + mi * 16) * 80 + aKb);
            #pragma unroll
            for (int mi = 0; mi < 4; mi++)
                #pragma unroll
                for (int p = 0; p < 2; p++) {
                    MMA16816(acc[mi][p * 2 + 0], FA[mi], FB[p][0], FB[p][1]);
                    MMA16816(acc[mi][p * 2 + 1], FA[mi], FB[p][2], FB[p][3]);
                }
        }
    }

    {
        float* GB = g_G + (size_t)b * CC * HW + p0;
        const int g = lane >> 2, t4 = lane & 3;
        #pragma unroll
        for (int mi = 0; mi < 4; mi++) {
            const int row = m0 + wm * 64 + mi * 16 + g;
            #pragma unroll
            for (int nb = 0; nb < 4; nb++) {
                const int px = wn * 32 + nb * 8 + t4 * 2;
                *(float2*)(GB + (size_t)row * HW + px) =
                    make_float2(acc[mi][nb][0], acc[mi][nb][1]);
                *(float2*)(GB + (size_t)(row + 8) * HW + px) =
                    make_float2(acc[mi][nb][2], acc[mi][nb][3]);
            }
        }
    }

    if (doBeta) {
        __syncthreads();
        float* bsm = (float*)(sm + SMAH);
        #pragma unroll
        for (int j = 0; j < 16; j += 4)
            *(float4*)(bsm + t * 16 + j) =
                make_float4(bacc[j], bacc[j + 1], bacc[j + 2], bacc[j + 3]);
        __syncthreads();
        if (t < 128) {
            const int slot = t >> 4, jj = t & 15;
            float s = 0.f;
            #pragma unroll 8
            for (int kg = 0; kg < 32; kg++)
                s += bsm[(kg * 8 + slot) * 16 + jj];
            g_beta[b * HW + p0 + t] = s;
        }
    }
}

// ============ shared tile geometry for the attention kernels ============
#define TW   32
#define TH   8
#define HALO 4
#define SW   (TW + 2 * HALO)   // 40
#define SH   (TH + 2 * HALO)   // 16
#define SN   (SH * SW)         // 640
#define CH   4
#define SNC  (SN * CH)         // 2560
#define NGH  (128 / CH)        // 32 groups per half

#define STAGE_MAP()                                                     \
    int  soff[10];                                                      \
    bool svld[10];                                                      \
    _Pragma("unroll")                                                   \
    for (int j = 0; j < 10; j++) {                                      \
        int idx = t + j * 256;                                          \
        int q = idx / SN, i = idx - q * SN;                             \
        int r = i / SW, cc = i - r * SW;                                \
        int hh = h0 - HALO + r, ww = w0 - HALO + cc;                    \
        svld[j] = ((unsigned)hh < HH_) && ((unsigned)ww < WW_);         \
        soff[j] = q * HW + hh * WW_ + ww;                               \
    }                                                                   \
    float stg[10];

#define GLOAD(src)                                             \
    { _Pragma("unroll")                                        \
      for (int j = 0; j < 10; j++)                             \
          stg[j] = svld[j] ? (src)[soff[j]] : 0.f; }
#define GSTORE(dst)                                            \
    { _Pragma("unroll")                                        \
      for (int j = 0; j < 10; j++)                             \
          (dst)[t + j * 256] = stg[j]; }

// ====== Kernel Attn1: partial logits over one 128-channel half ======
__global__ void __launch_bounds__(256, 2) kAttn1(const float* __restrict__ Fte) {
    __shared__ float Sh[2][SNC];
    const int t  = threadIdx.x;
    const int tx = t & 31, ty = t >> 5;
    const int zz = blockIdx.z;
    const int b = zz >> 1, half = zz & 1;
    const int w0 = blockIdx.x * TW, h0 = blockIdx.y * TH;
    const int h = h0 + ty, w = w0 + tx;
    const int pix = h * WW_ + w;
    const size_t plane = (size_t)b * CC * HW + (size_t)half * 128 * HW;

    STAGE_MAP();

    float lg[NK];
    #pragma unroll
    for (int k = 0; k < NK; k++) lg[k] = 0.f;

    const float* Gb = g_G + plane;
    const float* Fb = Fte + plane;
    GLOAD(Gb);
    GSTORE(Sh[0]);
    GLOAD(Gb + CH * HW);
    float fe[CH], fen[CH];
    #pragma unroll
    for (int cc = 0; cc < CH; cc++) fe[cc] = Fb[(size_t)cc * HW + pix];
    for (int g = 0; g < NGH; g++) {
        const int buf = g & 1;
        __syncthreads();
        if (g + 1 < NGH) GSTORE(Sh[buf ^ 1]);
        if (g + 2 < NGH) GLOAD(Gb + (size_t)(g + 2) * CH * HW);
        #pragma unroll
        for (int cc = 0; cc < CH; cc++)
            fen[cc] = (g + 1 < NGH) ? Fb[(size_t)((g + 1) * CH + cc) * HW + pix] : 0.f;
        const float* S = Sh[buf];
        const int sbase = (ty + HALO) * SW + (tx + HALO);
        #pragma unroll
        for (int cc = 0; cc < CH; cc++) {
            const float fc = fe[cc];
            const float* Sc = S + cc * SN;
            #pragma unroll
            for (int k = 0; k < NK; k++)
                lg[k] += fc * Sc[sbase + offA(k) * SW + offB(k)];
        }
        #pragma unroll
        for (int cc = 0; cc < CH; cc++) fe[cc] = fen[cc];
    }

    float* dst = g_part + (size_t)half * NK * NPIX + b * HW + pix;
    #pragma unroll
    for (int k = 0; k < NK; k++) dst[(size_t)k * NPIX] = lg[k];
}

// ====== Kernel Attn2: combine + softmax + aggregate one half ======
__global__ void __launch_bounds__(256, 2) kAttn2(const float* __restrict__ Ft,
                                                 float* __restrict__ out) {
    __shared__ float Sh[2][SNC];
    const int t  = threadIdx.x;
    const int tx = t & 31, ty = t >> 5;
    const int zz = blockIdx.z;
    const int b = zz >> 1, half = zz & 1;
    const int w0 = blockIdx.x * TW, h0 = blockIdx.y * TH;
    const int h = h0 + ty, w = w0 + tx;
    const int pix = h * WW_ + w;
    const size_t plane = (size_t)b * CC * HW + (size_t)half * 128 * HW;
    const int sbase = (ty + HALO) * SW + (tx + HALO);

    STAGE_MAP();

    // beta halo + validity mask
    #pragma unroll
    for (int j = 0; j < 3; j++) {
        int i = t + j * 256;
        if (i < SN) {
            int r = i / SW, cc = i - r * SW;
            int hh = h0 - HALO + r, ww = w0 - HALO + cc;
            bool v = ((unsigned)hh < HH_) && ((unsigned)ww < WW_);
            Sh[0][i] = v ? g_beta[b * HW + hh * WW_ + ww] : 0.f;
        }
    }
    __syncthreads();
    float lg[NK];
    #pragma unroll
    for (int k = 0; k < NK; k++) {
        const int a = offA(k), bo = offB(k);
        const bool valid = ((unsigned)(h + a) < HH_) && ((unsigned)(w + bo) < WW_);
        lg[k] = valid ? Sh[0][sbase + a * SW + bo] : -1e30f;
    }
    __syncthreads();

    // combine partial halves
    const float* pP = g_part + b * HW + pix;
    #pragma unroll
    for (int k = 0; k < NK; k++)
        lg[k] += pP[(size_t)k * NPIX] + pP[(size_t)(NK + k) * NPIX];

    // softmax over 33
    float m = lg[0];
    #pragma unroll
    for (int k = 1; k < NK; k++) m = fmaxf(m, lg[k]);
    float s = 0.f;
    #pragma unroll
    for (int k = 0; k < NK; k++) { lg[k] = expf(lg[k] - m); s += lg[k]; }
    const float inv = 1.0f / s;
    #pragma unroll
    for (int k = 0; k < NK; k++) lg[k] *= inv;

    // aggregate this half's 128 channels
    const float* Fa = Ft + plane;
    float*       Ob = out + plane;
    GLOAD(Fa);
    GSTORE(Sh[0]);
    GLOAD(Fa + CH * HW);
    for (int g = 0; g < NGH; g++) {
        const int buf = g & 1;
        __syncthreads();
        if (g + 1 < NGH) GSTORE(Sh[buf ^ 1]);
        if (g + 2 < NGH) GLOAD(Fa + (size_t)(g + 2) * CH * HW);
        const float* S = Sh[buf];
        #pragma unroll
        for (int cc = 0; cc < CH; cc++) {
            const float* Sc = S + cc * SN;
            float acc = 0.f;
            #pragma unroll
            for (int k = 0; k < NK; k++)
                acc += lg[k] * Sc[sbase + offA(k) * SW + offB(k)];
            Ob[(size_t)(g * CH + cc) * HW + pix] = acc;
        }
    }
}

// =================================== launch ======================================
extern "C" void kernel_launch(void* const* d_in, const int* in_sizes, int n_in,
                              void* d_out, int out_size) {
    const float* Ft  = (const float*)d_in[0];
    const float* Fte = (const float*)d_in[1];
    const float* Wf  = (const float*)d_in[2];
    const float* Wg  = (const float*)d_in[4];
    const float* bg  = (const float*)d_in[5];
    float* out = (float*)d_out;

    kMt<<<dim3(16, 16), dim3(16, 16)>>>(Wf, Wg);
    kV<<<1, 256>>>(Wf, bg);
    kG<<<dim3(HW / 128, 2, BATCH), 256>>>(Ft);
    kAttn1<<<dim3(WW_ / TW, HH_ / TH, BATCH * 2), 256>>>(Fte);
    kAttn2<<<dim3(WW_ / TW, HH_ / TH, BATCH * 2), 256>>>(Ft, out);
}

// round 8
// speedup vs baseline: 2.2238x; 1.0856x over previous
#include <cuda_runtime.h>
#include <cuda_bf16.h>
#include <cstdint>
#include <cstddef>

// Problem constants
#define BATCH 4
#define CC    256
#define HH_   96
#define WW_   96
#define HW    (HH_ * WW_)        // 9216
#define NPIX  (BATCH * HW)       // 36864
#define NK    33

// ---------------- device scratch ----------------
__device__ __nv_bfloat16 g_MtHi[CC * CC];
__device__ __nv_bfloat16 g_MtLo[CC * CC];
__device__ float g_v[CC];
__device__ float g_G[(size_t)BATCH * CC * HW];
__device__ float g_beta[NPIX];
__device__ float g_part[(size_t)2 * NK * NPIX];   // per-half partial logits, 9.7MB

// ---------------- star offsets ----------------
__host__ __device__ constexpr int offA(int k) {
    if (k == 0) return 0;
    int s = (k - 1) / 8 + 1, r = (k - 1) % 8;
    int a = (r < 3) ? -1 : (r < 5 ? 0 : 1);
    return a * s;
}
__host__ __device__ constexpr int offB(int k) {
    if (k == 0) return 0;
    int s = (k - 1) / 8 + 1, r = (k - 1) % 8;
    int b = (r < 3) ? (r - 1) : (r == 3 ? -1 : (r == 4 ? 1 : r - 6));
    return b * s;
}

// ---------------- helpers ----------------
__device__ __forceinline__ uint32_t smem_u32(const void* p) {
    uint32_t a;
    asm("{ .reg .u64 t; cvta.to.shared.u64 t, %1; cvt.u32.u64 %0, t; }" : "=r"(a) : "l"(p));
    return a;
}
__device__ __forceinline__ void ldmx4(uint32_t* r, uint32_t a) {
    asm volatile("ldmatrix.sync.aligned.m8n8.x4.shared.b16 {%0,%1,%2,%3}, [%4];"
                 : "=r"(r[0]), "=r"(r[1]), "=r"(r[2]), "=r"(r[3]) : "r"(a));
}
__device__ __forceinline__ void ldmx4t(uint32_t* r, uint32_t a) {
    asm volatile("ldmatrix.sync.aligned.m8n8.x4.trans.shared.b16 {%0,%1,%2,%3}, [%4];"
                 : "=r"(r[0]), "=r"(r[1]), "=r"(r[2]), "=r"(r[3]) : "r"(a));
}
#define MMA16816(acc, a, b0, b1)                                              \
    asm volatile("mma.sync.aligned.m16n8k16.row.col.f32.bf16.bf16.f32 "       \
                 "{%0,%1,%2,%3},{%4,%5,%6,%7},{%8,%9},{%0,%1,%2,%3};"         \
                 : "+f"((acc)[0]), "+f"((acc)[1]), "+f"((acc)[2]), "+f"((acc)[3]) \
                 : "r"((a)[0]), "r"((a)[1]), "r"((a)[2]), "r"((a)[3]),        \
                   "r"(b0), "r"(b1))

__device__ __forceinline__ uint32_t packHi(float x, float y) {
    __nv_bfloat162 h = __floats2bfloat162_rn(x, y);
    return *reinterpret_cast<uint32_t*>(&h);
}
__device__ __forceinline__ uint32_t packLo(float x, float y, uint32_t hpack) {
    __nv_bfloat162 h = *reinterpret_cast<__nv_bfloat162*>(&hpack);
    __nv_bfloat162 l = __floats2bfloat162_rn(x - __bfloat162float(h.x),
                                             y - __bfloat162float(h.y));
    return *reinterpret_cast<uint32_t*>(&l);
}

// ================= Kernel A: Mt = Wg^T Wf, split to bf16 hi/lo ================
__global__ void kMt(const float* __restrict__ Wf, const float* __restrict__ Wg) {
    __shared__ float gs[32][16];
    __shared__ float fs[32][16];
    const int tx = threadIdx.x, ty = threadIdx.y;
    const int t  = ty * 16 + tx;
    const int c1b = blockIdx.y * 16, c2b = blockIdx.x * 16;
    float acc = 0.f;
    for (int o0 = 0; o0 < CC; o0 += 32) {
        #pragma unroll
        for (int j = 0; j < 2; j++) {
            int i = t + j * 256;
            int r = i >> 4, q = i & 15;
            gs[r][q] = Wg[(o0 + r) * CC + c1b + q];
            fs[r][q] = Wf[(o0 + r) * CC + c2b + q];
        }
        __syncthreads();
        #pragma unroll
        for (int o = 0; o < 32; o++) acc += gs[o][ty] * fs[o][tx];
        __syncthreads();
    }
    __nv_bfloat16 hi = __float2bfloat16_rn(acc);
    __nv_bfloat16 lo = __float2bfloat16_rn(acc - __bfloat162float(hi));
    g_MtHi[(c1b + ty) * CC + (c2b + tx)] = hi;
    g_MtLo[(c1b + ty) * CC + (c2b + tx)] = lo;
}

// ================= Kernel V: v[c] = sum_o Wf[o,c]*bg[o] ========================
__global__ void kV(const float* __restrict__ Wf, const float* __restrict__ bg) {
    __shared__ float bgs[CC];
    const int c = threadIdx.x;
    bgs[c] = bg[c];
    __syncthreads();
    float acc = 0.f;
    #pragma unroll 8
    for (int o = 0; o < CC; o++) acc += Wf[o * CC + c] * bgs[o];
    g_v[c] = acc;
}

// ================= Kernel G: HMMA bf16-split GEMM + fused beta =================
// Software-pipelined: gmem loads for chunk kc+1 issued before compute of kc.
#define SMV   0
#define SMAH  1024
#define SMAL  (SMAH + 128 * 80)      // 11264
#define SMBH  (SMAL + 128 * 80)      // 21504
#define SMBL  (SMBH + 8192)          // 29696
#define SMTOT (SMBL + 8192)          // 37888

__global__ void __launch_bounds__(256) kG(const float* __restrict__ Ft) {
    __shared__ __align__(16) char sm[SMTOT];
    const uint32_t sb = smem_u32(sm);
    const int t = threadIdx.x;
    const int lane = t & 31, wid = t >> 5;
    const int wm = wid & 1, wn = wid >> 1;          // warp 64(M) x 32(N)

    const int b  = blockIdx.z;
    const int p0 = blockIdx.x * 128;
    const int m0 = blockIdx.y * 128;
    const bool doBeta = (blockIdx.y == 0);
    const float* FtB = Ft + (size_t)b * CC * HW + p0;

    float* vs = (float*)(sm + SMV);
    vs[t] = g_v[t];

    float acc[4][4][4];
    #pragma unroll
    for (int i = 0; i < 4; i++)
        #pragma unroll
        for (int j = 0; j < 4; j++)
            #pragma unroll
            for (int r = 0; r < 4; r++) acc[i][j][r] = 0.f;
    float bacc[16];
    #pragma unroll
    for (int j = 0; j < 16; j++) bacc[j] = 0.f;

    const int arow = t >> 1;
    const int kq   = t >> 3;
    const int nslt = t & 7;

    // ---- register prefetch buffers (chunk kc+1 loaded during compute of kc) ----
    uint4  pah[2], pal[2];       // A hi/lo, j=0,1
    float4 pb[4];                // B fp32, c-chunk {0,1} x {f0,f1}

#define LOAD_CHUNK(k0)                                                          \
    { _Pragma("unroll")                                                         \
      for (int j = 0; j < 2; j++) {                                             \
          const int ch = (t & 1) * 2 + j;                                       \
          const size_t src = (size_t)(m0 + arow) * (CC * 2) + (size_t)(k0) * 2 + ch * 16; \
          pah[j] = *(const uint4*)((const char*)g_MtHi + src);                  \
          pal[j] = *(const uint4*)((const char*)g_MtLo + src);                  \
      }                                                                         \
      { const float* srcB = FtB + (size_t)((k0) + kq) * HW + nslt * 16;         \
        _Pragma("unroll")                                                       \
        for (int c = 0; c < 2; c++) {                                           \
            pb[c * 2 + 0] = *(const float4*)(srcB + c * 8);                     \
            pb[c * 2 + 1] = *(const float4*)(srcB + c * 8 + 4);                 \
        } } }

    LOAD_CHUNK(0);

    for (int kc = 0; kc < 8; kc++) {
        const int k0 = kc * 32;
        __syncthreads();                          // previous compute done with smem
        // ---- store A from regs ----
        #pragma unroll
        for (int j = 0; j < 2; j++) {
            const int ch = (t & 1) * 2 + j;
            *(uint4*)(sm + SMAH + arow * 80 + ch * 16) = pah[j];
            *(uint4*)(sm + SMAL + arow * 80 + ch * 16) = pal[j];
        }
        // ---- convert + store B from regs, beta FMA ----
        {
            const float vk = vs[k0 + kq];
            #pragma unroll
            for (int c = 0; c < 2; c++) {
                float4 f0 = pb[c * 2 + 0];
                float4 f1 = pb[c * 2 + 1];
                uint32_t h0 = packHi(f0.x, f0.y), h1 = packHi(f0.z, f0.w);
                uint32_t h2 = packHi(f1.x, f1.y), h3 = packHi(f1.z, f1.w);
                uint32_t l0 = packLo(f0.x, f0.y, h0), l1 = packLo(f0.z, f0.w, h1);
                uint32_t l2 = packLo(f1.x, f1.y, h2), l3 = packLo(f1.z, f1.w, h3);
                const int ch = ((nslt * 2 + c) ^ (kq & 7));
                *(uint4*)(sm + SMBH + kq * 256 + ch * 16) = make_uint4(h0, h1, h2, h3);
                *(uint4*)(sm + SMBL + kq * 256 + ch * 16) = make_uint4(l0, l1, l2, l3);
                if (doBeta) {
                    bacc[c * 8 + 0] = fmaf(vk, f0.x, bacc[c * 8 + 0]);
                    bacc[c * 8 + 1] = fmaf(vk, f0.y, bacc[c * 8 + 1]);
                    bacc[c * 8 + 2] = fmaf(vk, f0.z, bacc[c * 8 + 2]);
                    bacc[c * 8 + 3] = fmaf(vk, f0.w, bacc[c * 8 + 3]);
                    bacc[c * 8 + 4] = fmaf(vk, f1.x, bacc[c * 8 + 4]);
                    bacc[c * 8 + 5] = fmaf(vk, f1.y, bacc[c * 8 + 5]);
                    bacc[c * 8 + 6] = fmaf(vk, f1.z, bacc[c * 8 + 6]);
                    bacc[c * 8 + 7] = fmaf(vk, f1.w, bacc[c * 8 + 7]);
                }
            }
        }
        __syncthreads();                          // smem ready for compute
        if (kc + 1 < 8) LOAD_CHUNK(k0 + 32);      // prefetch next chunk (hidden by MMA)
        // ---- compute: 2 k16 steps x 3 terms ----
        #pragma unroll
        for (int ks = 0; ks < 2; ks++) {
            const int kk = ks * 16;
            const int aRow = wm * 64 + (lane & 15);
            const int aKb  = kk * 2 + (lane & 16);
            const int bK   = kk + (lane & 15);
            uint32_t FA[4][4], FB[2][4], FB2[2][4];
            #pragma unroll
            for (int mi = 0; mi < 4; mi++)
                ldmx4(FA[mi], sb + SMAH + (aRow + mi * 16) * 80 + aKb);
            #pragma unroll
            for (int p = 0; p < 2; p++) {
                const int nb = wn * 64 + p * 32 + (lane & 16);
                const int ch = ((nb >> 4) ^ (bK & 7));
                ldmx4t(FB[p], sb + SMBH + bK * 256 + (ch << 4));
            }
            #pragma unroll
            for (int mi = 0; mi < 4; mi++)
                #pragma unroll
                for (int p = 0; p < 2; p++) {
                    MMA16816(acc[mi][p * 2 + 0], FA[mi], FB[p][0], FB[p][1]);
                    MMA16816(acc[mi][p * 2 + 1], FA[mi], FB[p][2], FB[p][3]);
                }
            #pragma unroll
            for (int p = 0; p < 2; p++) {
                const int nb = wn * 64 + p * 32 + (lane & 16);
                const int ch = ((nb >> 4) ^ (bK & 7));
                ldmx4t(FB2[p], sb + SMBL + bK * 256 + (ch << 4));
            }
            #pragma unroll
            for (int mi = 0; mi < 4; mi++)
                #pragma unroll
                for (int p = 0; p < 2; p++) {
                    MMA16816(acc[mi][p * 2 + 0], FA[mi], FB2[p][0], FB2[p][1]);
                    MMA16816(acc[mi][p * 2 + 1], FA[mi], FB2[p][2], FB2[p][3]);
                }
            #pragma unroll
            for (int mi = 0; mi < 4; mi++)
                ldmx4(FA[mi], sb + SMAL + (aRow + mi * 16) * 80 + aKb);
            #pragma unroll
            for (int mi = 0; mi < 4; mi++)
                #pragma unroll
                for (int p = 0; p < 2; p++) {
                    MMA16816(acc[mi][p * 2 + 0], FA[mi], FB[p][0], FB[p][1]);
                    MMA16816(acc[mi][p * 2 + 1], FA[mi], FB[p][2], FB[p][3]);
                }
        }
    }
#undef LOAD_CHUNK

    {
        float* GB = g_G + (size_t)b * CC * HW + p0;
        const int g = lane >> 2, t4 = lane & 3;
        #pragma unroll
        for (int mi = 0; mi < 4; mi++) {
            const int row = m0 + wm * 64 + mi * 16 + g;
            #pragma unroll
            for (int nb = 0; nb < 4; nb++) {
                const int px = wn * 32 + nb * 8 + t4 * 2;
                *(float2*)(GB + (size_t)row * HW + px) =
                    make_float2(acc[mi][nb][0], acc[mi][nb][1]);
                *(float2*)(GB + (size_t)(row + 8) * HW + px) =
                    make_float2(acc[mi][nb][2], acc[mi][nb][3]);
            }
        }
    }

    if (doBeta) {
        __syncthreads();
        float* bsm = (float*)(sm + SMAH);
        #pragma unroll
        for (int j = 0; j < 16; j += 4)
            *(float4*)(bsm + t * 16 + j) =
                make_float4(bacc[j], bacc[j + 1], bacc[j + 2], bacc[j + 3]);
        __syncthreads();
        if (t < 128) {
            const int slot = t >> 4, jj = t & 15;
            float s = 0.f;
            #pragma unroll 8
            for (int kg = 0; kg < 32; kg++)
                s += bsm[(kg * 8 + slot) * 16 + jj];
            g_beta[b * HW + p0 + t] = s;
        }
    }
}

// ============ shared tile geometry for the attention kernels ============
#define TW   32
#define TH   8
#define HALO 4
#define SW   (TW + 2 * HALO)   // 40
#define SH   (TH + 2 * HALO)   // 16
#define SN   (SH * SW)         // 640
#define CH   4
#define SNC  (SN * CH)         // 2560
#define NGH  (128 / CH)        // 32 groups per half

#define STAGE_MAP()                                                     \
    int  soff[10];                                                      \
    bool svld[10];                                                      \
    _Pragma("unroll")                                                   \
    for (int j = 0; j < 10; j++) {                                      \
        int idx = t + j * 256;                                          \
        int q = idx / SN, i = idx - q * SN;                             \
        int r = i / SW, cc = i - r * SW;                                \
        int hh = h0 - HALO + r, ww = w0 - HALO + cc;                    \
        svld[j] = ((unsigned)hh < HH_) && ((unsigned)ww < WW_);         \
        soff[j] = q * HW + hh * WW_ + ww;                               \
    }                                                                   \
    float stg[10];

#define GLOAD(src)                                             \
    { _Pragma("unroll")                                        \
      for (int j = 0; j < 10; j++)                             \
          stg[j] = svld[j] ? (src)[soff[j]] : 0.f; }
#define GSTORE(dst)                                            \
    { _Pragma("unroll")                                        \
      for (int j = 0; j < 10; j++)                             \
          (dst)[t + j * 256] = stg[j]; }

// ====== Kernel Attn1: partial logits over one 128-channel half ======
__global__ void __launch_bounds__(256, 2) kAttn1(const float* __restrict__ Fte) {
    __shared__ float Sh[2][SNC];
    const int t  = threadIdx.x;
    const int tx = t & 31, ty = t >> 5;
    const int zz = blockIdx.z;
    const int b = zz >> 1, half = zz & 1;
    const int w0 = blockIdx.x * TW, h0 = blockIdx.y * TH;
    const int h = h0 + ty, w = w0 + tx;
    const int pix = h * WW_ + w;
    const size_t plane = (size_t)b * CC * HW + (size_t)half * 128 * HW;

    STAGE_MAP();

    float lg[NK];
    #pragma unroll
    for (int k = 0; k < NK; k++) lg[k] = 0.f;

    const float* Gb = g_G + plane;
    const float* Fb = Fte + plane;
    GLOAD(Gb);
    GSTORE(Sh[0]);
    GLOAD(Gb + CH * HW);
    float fe[CH], fen[CH];
    #pragma unroll
    for (int cc = 0; cc < CH; cc++) fe[cc] = Fb[(size_t)cc * HW + pix];
    for (int g = 0; g < NGH; g++) {
        const int buf = g & 1;
        __syncthreads();
        if (g + 1 < NGH) GSTORE(Sh[buf ^ 1]);
        if (g + 2 < NGH) GLOAD(Gb + (size_t)(g + 2) * CH * HW);
        #pragma unroll
        for (int cc = 0; cc < CH; cc++)
            fen[cc] = (g + 1 < NGH) ? Fb[(size_t)((g + 1) * CH + cc) * HW + pix] : 0.f;
        const float* S = Sh[buf];
        const int sbase = (ty + HALO) * SW + (tx + HALO);
        #pragma unroll
        for (int cc = 0; cc < CH; cc++) {
            const float fc = fe[cc];
            const float* Sc = S + cc * SN;
            #pragma unroll
            for (int k = 0; k < NK; k++)
                lg[k] += fc * Sc[sbase + offA(k) * SW + offB(k)];
        }
        #pragma unroll
        for (int cc = 0; cc < CH; cc++) fe[cc] = fen[cc];
    }

    float* dst = g_part + (size_t)half * NK * NPIX + b * HW + pix;
    #pragma unroll
    for (int k = 0; k < NK; k++) dst[(size_t)k * NPIX] = lg[k];
}

// ====== Kernel Attn2: combine + softmax + aggregate one half ======
__global__ void __launch_bounds__(256, 2) kAttn2(const float* __restrict__ Ft,
                                                 float* __restrict__ out) {
    __shared__ float Sh[2][SNC];
    const int t  = threadIdx.x;
    const int tx = t & 31, ty = t >> 5;
    const int zz = blockIdx.z;
    const int b = zz >> 1, half = zz & 1;
    const int w0 = blockIdx.x * TW, h0 = blockIdx.y * TH;
    const int h = h0 + ty, w = w0 + tx;
    const int pix = h * WW_ + w;
    const size_t plane = (size_t)b * CC * HW + (size_t)half * 128 * HW;
    const int sbase = (ty + HALO) * SW + (tx + HALO);

    STAGE_MAP();

    // beta halo + validity mask
    #pragma unroll
    for (int j = 0; j < 3; j++) {
        int i = t + j * 256;
        if (i < SN) {
            int r = i / SW, cc = i - r * SW;
            int hh = h0 - HALO + r, ww = w0 - HALO + cc;
            bool v = ((unsigned)hh < HH_) && ((unsigned)ww < WW_);
            Sh[0][i] = v ? g_beta[b * HW + hh * WW_ + ww] : 0.f;
        }
    }
    __syncthreads();
    float lg[NK];
    #pragma unroll
    for (int k = 0; k < NK; k++) {
        const int a = offA(k), bo = offB(k);
        const bool valid = ((unsigned)(h + a) < HH_) && ((unsigned)(w + bo) < WW_);
        lg[k] = valid ? Sh[0][sbase + a * SW + bo] : -1e30f;
    }
    __syncthreads();

    // combine partial halves
    const float* pP = g_part + b * HW + pix;
    #pragma unroll
    for (int k = 0; k < NK; k++)
        lg[k] += pP[(size_t)k * NPIX] + pP[(size_t)(NK + k) * NPIX];

    // softmax over 33
    float m = lg[0];
    #pragma unroll
    for (int k = 1; k < NK; k++) m = fmaxf(m, lg[k]);
    float s = 0.f;
    #pragma unroll
    for (int k = 0; k < NK; k++) { lg[k] = expf(lg[k] - m); s += lg[k]; }
    const float inv = 1.0f / s;
    #pragma unroll
    for (int k = 0; k < NK; k++) lg[k] *= inv;

    // aggregate this half's 128 channels
    const float* Fa = Ft + plane;
    float*       Ob = out + plane;
    GLOAD(Fa);
    GSTORE(Sh[0]);
    GLOAD(Fa + CH * HW);
    for (int g = 0; g < NGH; g++) {
        const int buf = g & 1;
        __syncthreads();
        if (g + 1 < NGH) GSTORE(Sh[buf ^ 1]);
        if (g + 2 < NGH) GLOAD(Fa + (size_t)(g + 2) * CH * HW);
        const float* S = Sh[buf];
        #pragma unroll
        for (int cc = 0; cc < CH; cc++) {
            const float* Sc = S + cc * SN;
            float acc = 0.f;
            #pragma unroll
            for (int k = 0; k < NK; k++)
                acc += lg[k] * Sc[sbase + offA(k) * SW + offB(k)];
            Ob[(size_t)(g * CH + cc) * HW + pix] = acc;
        }
    }
}

// =================================== launch ======================================
extern "C" void kernel_launch(void* const* d_in, const int* in_sizes, int n_in,
                              void* d_out, int out_size) {
    const float* Ft  = (const float*)d_in[0];
    const float* Fte = (const float*)d_in[1];
    const float* Wf  = (const float*)d_in[2];
    const float* Wg  = (const float*)d_in[4];
    const float* bg  = (const float*)d_in[5];
    float* out = (float*)d_out;

    kMt<<<dim3(16, 16), dim3(16, 16)>>>(Wf, Wg);
    kV<<<1, 256>>>(Wf, bg);
    kG<<<dim3(HW / 128, 2, BATCH), 256>>>(Ft);
    kAttn1<<<dim3(WW_ / TW, HH_ / TH, BATCH * 2), 256>>>(Fte);
    kAttn2<<<dim3(WW_ / TW, HH_ / TH, BATCH * 2), 256>>>(Ft, out);
}